// round 3
// baseline (speedup 1.0000x reference)
#include <cuda_runtime.h>
#include <math.h>

// Problem dims
#define HH 128
#define WW 128
#define BB 8
#define DD 128
#define MM (HH*WW*BB)          // 131072 rows
// element offset for (h,w,b,d) in a [M,128] tensor: ((h*1024 + w*8 + b)*128 + d)

// ---------------- scratch (no cudaMalloc allowed) ----------------
__device__ float  g_inp [MM * 256];   // silu(x@W_in + b_in), interleaved re/im lanes
__device__ float  g_gate[MM * 256];   // silu(x@W_gate + b_gate)
__device__ float  g_lam [MM * 128];   // sigmoid(x@W_lambda + b_lambda)
__device__ float2 g_acc [MM * 128];   // sum of 4 scans: (.x = hr, .y = hi)

static __device__ __forceinline__ float sigmoidf_(float v) {
    return 1.0f / (1.0f + expf(-v));
}

// =====================================================================
// K1: x(M x 128) @ [W_in | W_gate | W_lambda](128 x 640)  + bias + act
//     BM=64, BN=64, full K=128 resident. 256 threads, 4x4 microtile.
// =====================================================================
__global__ void k1_in_gemm(const float* __restrict__ x,
                           const float* __restrict__ Win, const float* __restrict__ bin,
                           const float* __restrict__ Wl,  const float* __restrict__ bl,
                           const float* __restrict__ Wg,  const float* __restrict__ bg)
{
    extern __shared__ float sm[];
    float* As = sm;             // [64][128]
    float* Bs = sm + 64 * 128;  // [128][64]

    const int tid = threadIdx.x;
    const int m0 = blockIdx.y * 64;
    const int n0 = blockIdx.x * 64;

    // Load A tile (64 rows of x) with float4
    {
        const float4* xr = (const float4*)(x + (size_t)m0 * 128);
        float4* As4 = (float4*)As;
#pragma unroll
        for (int t = 0; t < 8; t++) {
            int idx = tid + t * 256;      // 2048 float4 total
            As4[idx] = xr[idx];
        }
    }
    // Load B tile (128 x 64 cols of the concatenated weight)
    {
#pragma unroll
        for (int t = 0; t < 32; t++) {
            int idx = tid + t * 256;      // 8192 scalars
            int k  = idx >> 6;
            int nl = idx & 63;
            int n  = n0 + nl;
            float v;
            if (n < 256)      v = Win[k * 256 + n];
            else if (n < 512) v = Wg [k * 256 + (n - 256)];
            else              v = Wl [k * 128 + (n - 512)];
            Bs[k * 64 + nl] = v;
        }
    }
    __syncthreads();

    const int ty = tid >> 4;
    const int tx = tid & 15;
    float acc[4][4] = {};

#pragma unroll 4
    for (int k = 0; k < 128; k++) {
        float a0 = As[(ty * 4 + 0) * 128 + k];
        float a1 = As[(ty * 4 + 1) * 128 + k];
        float a2 = As[(ty * 4 + 2) * 128 + k];
        float a3 = As[(ty * 4 + 3) * 128 + k];
        float4 b = *(const float4*)&Bs[k * 64 + tx * 4];
        acc[0][0] += a0 * b.x; acc[0][1] += a0 * b.y; acc[0][2] += a0 * b.z; acc[0][3] += a0 * b.w;
        acc[1][0] += a1 * b.x; acc[1][1] += a1 * b.y; acc[1][2] += a1 * b.z; acc[1][3] += a1 * b.w;
        acc[2][0] += a2 * b.x; acc[2][1] += a2 * b.y; acc[2][2] += a2 * b.z; acc[2][3] += a2 * b.w;
        acc[3][0] += a3 * b.x; acc[3][1] += a3 * b.y; acc[3][2] += a3 * b.z; acc[3][3] += a3 * b.w;
    }

    // Epilogue: region is uniform per block (n0 is a multiple of 64)
#pragma unroll
    for (int i = 0; i < 4; i++) {
        int row = m0 + ty * 4 + i;
#pragma unroll
        for (int j = 0; j < 4; j++) {
            int n = n0 + tx * 4 + j;
            float v = acc[i][j];
            if (n < 256) {
                v += bin[n];
                g_inp[(size_t)row * 256 + n] = v * sigmoidf_(v);      // silu
            } else if (n < 512) {
                int nn = n - 256;
                v += bg[nn];
                g_gate[(size_t)row * 256 + nn] = v * sigmoidf_(v);    // silu
            } else {
                int nn = n - 512;
                v += bl[nn];
                g_lam[(size_t)row * 128 + nn] = sigmoidf_(v);         // lambda (LOWER_BOUND=0)
            }
        }
    }
}

// =====================================================================
// K2: scans along H (axis 0). fwd(theta_f) writes acc; rev(theta_r) RMW.
//     One thread per (w,b,d) line; stride between h steps = 131072 elems.
// =====================================================================
__global__ void k2_hscan(const float* __restrict__ thf, const float* __restrict__ thr_)
{
    int idx = blockIdx.x * blockDim.x + threadIdx.x;   // 0..131071
    int d  = idx & 127;
    int wb = idx >> 7;                                 // w*8+b
    int base = wb * 128 + d;

    const float2* __restrict__ inp2 = (const float2*)g_inp;

    // forward, theta_f
    {
        float t = thf[d];
        float cf = cosf(t), sf = sinf(t);
        float hr = 0.f, hi = 0.f;
        int off = base;
#pragma unroll 4
        for (int h = 0; h < 128; h++, off += 131072) {
            float lam = g_lam[off];
            float2 p  = inp2[off];
            float a = lam * cf, b = lam * sf, om = 1.f - lam;
            float nr = a * hr - b * hi + om * p.x;
            float ni = a * hi + b * hr + om * p.y;
            hr = nr; hi = ni;
            g_acc[off] = make_float2(hr, hi);
        }
    }
    // reverse, theta_r
    {
        float t = thr_[d];
        float cr = cosf(t), sr = sinf(t);
        float hr = 0.f, hi = 0.f;
        int off = base + 127 * 131072;
#pragma unroll 4
        for (int h = 0; h < 128; h++, off -= 131072) {
            float lam = g_lam[off];
            float2 p  = inp2[off];
            float a = lam * cr, b = lam * sr, om = 1.f - lam;
            float nr = a * hr - b * hi + om * p.x;
            float ni = a * hi + b * hr + om * p.y;
            hr = nr; hi = ni;
            float2 acc = g_acc[off];
            acc.x += hr; acc.y += hi;
            g_acc[off] = acc;
        }
    }
}

// =====================================================================
// K3: scans along W (axis 1). Both directions RMW into acc.
//     One thread per (h,b,d) line; stride between w steps = 1024 elems.
// =====================================================================
__global__ void k3_wscan(const float* __restrict__ thf, const float* __restrict__ thr_)
{
    int idx = blockIdx.x * blockDim.x + threadIdx.x;
    int d = idx & 127;
    int b = (idx >> 7) & 7;
    int h = idx >> 10;
    int base = (h * 1024 + b) * 128 + d;

    const float2* __restrict__ inp2 = (const float2*)g_inp;

    // forward, theta_f
    {
        float t = thf[d];
        float cf = cosf(t), sf = sinf(t);
        float hr = 0.f, hi = 0.f;
        int off = base;
#pragma unroll 4
        for (int w = 0; w < 128; w++, off += 1024) {
            float lam = g_lam[off];
            float2 p  = inp2[off];
            float a = lam * cf, bb = lam * sf, om = 1.f - lam;
            float nr = a * hr - bb * hi + om * p.x;
            float ni = a * hi + bb * hr + om * p.y;
            hr = nr; hi = ni;
            float2 acc = g_acc[off];
            acc.x += hr; acc.y += hi;
            g_acc[off] = acc;
        }
    }
    // reverse, theta_r
    {
        float t = thr_[d];
        float cr = cosf(t), sr = sinf(t);
        float hr = 0.f, hi = 0.f;
        int off = base + 127 * 1024;
#pragma unroll 4
        for (int w = 0; w < 128; w++, off -= 1024) {
            float lam = g_lam[off];
            float2 p  = inp2[off];
            float a = lam * cr, bb = lam * sr, om = 1.f - lam;
            float nr = a * hr - bb * hi + om * p.x;
            float ni = a * hi + bb * hr + om * p.y;
            hr = nr; hi = ni;
            float2 acc = g_acc[off];
            acc.x += hr; acc.y += hi;
            g_acc[off] = acc;
        }
    }
}

// =====================================================================
// K4: per 64-row block: LayerNorm(256) * ln_w + ln_b, * gate -> smem
//     feature tile, then GEMM @ W_out(256x128) + b_out -> out.
//     smem: feat 64x257 (pad) + Wout 256x128 = 196864 bytes.
// =====================================================================
__global__ void k4_out_gemm(const float* __restrict__ Wout, const float* __restrict__ bout,
                            const float* __restrict__ lnw,  const float* __restrict__ lnb,
                            float* __restrict__ out)
{
    extern __shared__ float sm[];
    float* feat = sm;              // [64][257]
    float* Ws   = sm + 64 * 257;   // [256][128]

    const int tid = threadIdx.x;
    const int m0 = blockIdx.x * 64;

    // Load W_out (256x128) with float4
    {
        float4* Ws4 = (float4*)Ws;
        const float4* W4 = (const float4*)Wout;
#pragma unroll
        for (int t = 0; t < 32; t++) Ws4[tid + t * 256] = W4[tid + t * 256];
    }

    // Producer: LN stats + normalized, gated feature into smem
    {
        int r = tid >> 2;          // local row 0..63
        int q = tid & 3;           // 4 lanes cooperate per row
        int row = m0 + r;
        const float2* accp = g_acc + (size_t)row * 128;

        float sum = 0.f, ss = 0.f;
#pragma unroll
        for (int t = 0; t < 32; t++) {
            int dd = q + t * 4;
            float2 v = accp[dd];
            sum += v.x + v.y;
            ss  += v.x * v.x + v.y * v.y;
        }
        sum += __shfl_xor_sync(0xffffffffu, sum, 1);
        sum += __shfl_xor_sync(0xffffffffu, sum, 2);
        ss  += __shfl_xor_sync(0xffffffffu, ss, 1);
        ss  += __shfl_xor_sync(0xffffffffu, ss, 2);

        float mu   = sum * (1.0f / 256.0f);
        float var  = ss * (1.0f / 256.0f) - mu * mu;
        float rstd = rsqrtf(var + 1e-5f);

        const float* gr = g_gate + (size_t)row * 256;
#pragma unroll
        for (int t = 0; t < 32; t++) {
            int dd = q + t * 4;
            float2 v = accp[dd];
            float fr = ((v.x - mu) * rstd * lnw[dd]       + lnb[dd])       * gr[dd];
            float fi = ((v.y - mu) * rstd * lnw[128 + dd] + lnb[128 + dd]) * gr[128 + dd];
            feat[r * 257 + dd]       = fr;
            feat[r * 257 + 128 + dd] = fi;
        }
    }
    __syncthreads();

    // GEMM: feat(64x256) @ Ws(256x128); 16x16 threads, 4x8 microtile
    const int ty = tid >> 4;
    const int tx = tid & 15;
    float c[4][8] = {};

#pragma unroll 4
    for (int k = 0; k < 256; k++) {
        float a0 = feat[(ty * 4 + 0) * 257 + k];
        float a1 = feat[(ty * 4 + 1) * 257 + k];
        float a2 = feat[(ty * 4 + 2) * 257 + k];
        float a3 = feat[(ty * 4 + 3) * 257 + k];
        float4 b0 = *(const float4*)&Ws[k * 128 + tx * 8];
        float4 b1 = *(const float4*)&Ws[k * 128 + tx * 8 + 4];
        c[0][0] += a0 * b0.x; c[0][1] += a0 * b0.y; c[0][2] += a0 * b0.z; c[0][3] += a0 * b0.w;
        c[0][4] += a0 * b1.x; c[0][5] += a0 * b1.y; c[0][6] += a0 * b1.z; c[0][7] += a0 * b1.w;
        c[1][0] += a1 * b0.x; c[1][1] += a1 * b0.y; c[1][2] += a1 * b0.z; c[1][3] += a1 * b0.w;
        c[1][4] += a1 * b1.x; c[1][5] += a1 * b1.y; c[1][6] += a1 * b1.z; c[1][7] += a1 * b1.w;
        c[2][0] += a2 * b0.x; c[2][1] += a2 * b0.y; c[2][2] += a2 * b0.z; c[2][3] += a2 * b0.w;
        c[2][4] += a2 * b1.x; c[2][5] += a2 * b1.y; c[2][6] += a2 * b1.z; c[2][7] += a2 * b1.w;
        c[3][0] += a3 * b0.x; c[3][1] += a3 * b0.y; c[3][2] += a3 * b0.z; c[3][3] += a3 * b0.w;
        c[3][4] += a3 * b1.x; c[3][5] += a3 * b1.y; c[3][6] += a3 * b1.z; c[3][7] += a3 * b1.w;
    }

#pragma unroll
    for (int i = 0; i < 4; i++) {
        int row = m0 + ty * 4 + i;
        float* op = out + (size_t)row * 128 + tx * 8;
#pragma unroll
        for (int j = 0; j < 8; j++) op[j] = c[i][j] + bout[tx * 8 + j];
    }
}

// =====================================================================
extern "C" void kernel_launch(void* const* d_in, const int* in_sizes, int n_in,
                              void* d_out, int out_size)
{
    const float* x    = (const float*)d_in[0];
    const float* Win  = (const float*)d_in[1];
    const float* bin  = (const float*)d_in[2];
    const float* Wl   = (const float*)d_in[3];
    const float* bl   = (const float*)d_in[4];
    const float* thf  = (const float*)d_in[5];
    const float* thr_ = (const float*)d_in[6];
    const float* Wg   = (const float*)d_in[7];
    const float* bg   = (const float*)d_in[8];
    const float* Wout = (const float*)d_in[9];
    const float* bout = (const float*)d_in[10];
    const float* lnw  = (const float*)d_in[11];
    const float* lnb  = (const float*)d_in[12];
    float* out = (float*)d_out;

    const int SM1 = (64 * 128 + 128 * 64) * 4;        // 65536
    const int SM4 = (64 * 257 + 256 * 128) * 4;       // 196864
    cudaFuncSetAttribute(k1_in_gemm,  cudaFuncAttributeMaxDynamicSharedMemorySize, SM1);
    cudaFuncSetAttribute(k4_out_gemm, cudaFuncAttributeMaxDynamicSharedMemorySize, SM4);

    dim3 g1(640 / 64, MM / 64);                        // (10, 2048)
    k1_in_gemm<<<g1, 256, SM1>>>(x, Win, bin, Wl, bl, Wg, bg);

    k2_hscan<<<MM / 256, 256>>>(thf, thr_);            // 512 blocks, 1 thread/line
    k3_wscan<<<MM / 256, 256>>>(thf, thr_);

    k4_out_gemm<<<MM / 64, 256, SM4>>>(Wout, bout, lnw, lnb, out);
}

// round 4
// speedup vs baseline: 1.2332x; 1.2332x over previous
#include <cuda_runtime.h>
#include <math.h>

// Problem dims
#define HH 128
#define WW 128
#define BB 8
#define DD 128
#define MM (HH*WW*BB)          // 131072 rows

typedef unsigned long long ull;

// ---------------- scratch (no cudaMalloc allowed) ----------------
__device__ float  g_inp [MM * 256];   // silu(x@W_in + b_in), interleaved re/im lanes
__device__ float  g_gate[MM * 256];   // silu(x@W_gate + b_gate)
__device__ float  g_lam [MM * 128];   // sigmoid(x@W_lambda + b_lambda)
__device__ float2 g_acc [MM * 128];   // sum of 4 scans: (.x = hr, .y = hi)

static __device__ __forceinline__ float sigmoidf_(float v) {
    return 1.0f / (1.0f + expf(-v));
}

// ---------------- packed fp32x2 helpers (sm_100 FFMA2 path) ----------------
static __device__ __forceinline__ ull pack2(float v) {
    ull r; asm("mov.b64 %0, {%1, %1};" : "=l"(r) : "f"(v)); return r;
}
static __device__ __forceinline__ void ffma2(ull &d, ull a, ull b) {
    asm("fma.rn.f32x2 %0, %1, %2, %0;" : "+l"(d) : "l"(a), "l"(b));
}
static __device__ __forceinline__ void lds2(ull &a, ull &b, unsigned addr) {
    asm volatile("ld.shared.v2.b64 {%0, %1}, [%2];" : "=l"(a), "=l"(b) : "r"(addr));
}
static __device__ __forceinline__ float2 unpack2(ull v) {
    float2 r; asm("mov.b64 {%0, %1}, %2;" : "=f"(r.x), "=f"(r.y) : "l"(v)); return r;
}

// =====================================================================
// K1: x(M x 128) @ [W_in | W_gate | W_lambda](128 x 640)  + bias + act
//     BM=128, BN=128, K=128. 256 threads, 8x8 microtile, FFMA2.
// =====================================================================
__global__ void __launch_bounds__(256, 1)
k1_in_gemm(const float* __restrict__ x,
           const float* __restrict__ Win, const float* __restrict__ bin,
           const float* __restrict__ Wl,  const float* __restrict__ bl,
           const float* __restrict__ Wg,  const float* __restrict__ bg)
{
    extern __shared__ float sm[];
    float* As = sm;              // [128][128] row-major (m, k)
    float* Bs = sm + 128 * 128;  // [128][128] (k, n)

    const int tid = threadIdx.x;
    const int m0 = blockIdx.y * 128;
    const int n0 = blockIdx.x * 128;

    // ---- load A tile (float4, coalesced row copies)
    {
        const float4* xr = (const float4*)(x + (size_t)m0 * 128);
        float4* As4 = (float4*)As;
#pragma unroll
        for (int t = 0; t < 16; t++) As4[tid + t * 256] = xr[tid + t * 256];
    }
    // ---- load B tile (region uniform per block since n0 is mult of 128)
    {
        const float* Wsrc; int ldn, c0;
        if (n0 < 256)      { Wsrc = Win; ldn = 256; c0 = n0; }
        else if (n0 < 512) { Wsrc = Wg;  ldn = 256; c0 = n0 - 256; }
        else               { Wsrc = Wl;  ldn = 128; c0 = 0; }
        float4* Bs4 = (float4*)Bs;
#pragma unroll
        for (int t = 0; t < 16; t++) {
            int idx = tid + t * 256;
            int k = idx >> 5, n4 = idx & 31;
            Bs4[idx] = *(const float4*)&Wsrc[k * ldn + c0 + n4 * 4];
        }
    }
    __syncthreads();

    const int ty = tid >> 4;     // 0..15 -> rows ty*8
    const int tx = tid & 15;     // 0..15 -> cols tx*8
    const unsigned bs_base = (unsigned)__cvta_generic_to_shared(Bs) + tx * 32;
    const float4* As4c = (const float4*)As;

    ull acc[8][4];
#pragma unroll
    for (int i = 0; i < 8; i++)
#pragma unroll
        for (int p = 0; p < 4; p++) acc[i][p] = 0ULL;

#pragma unroll 2
    for (int kc = 0; kc < 32; kc++) {
        ull b[4][4];
#pragma unroll
        for (int kk = 0; kk < 4; kk++) {
            unsigned ad = bs_base + (unsigned)((kc * 4 + kk) * 512);
            lds2(b[kk][0], b[kk][1], ad);
            lds2(b[kk][2], b[kk][3], ad + 16);
        }
#pragma unroll
        for (int i = 0; i < 8; i++) {
            float4 a = As4c[(ty * 8 + i) * 32 + kc];
            ull a0 = pack2(a.x), a1 = pack2(a.y), a2 = pack2(a.z), a3 = pack2(a.w);
#pragma unroll
            for (int p = 0; p < 4; p++) {
                ffma2(acc[i][p], a0, b[0][p]);
                ffma2(acc[i][p], a1, b[1][p]);
                ffma2(acc[i][p], a2, b[2][p]);
                ffma2(acc[i][p], a3, b[3][p]);
            }
        }
    }

    // ---- epilogue (region uniform per block)
    const int nb = tx * 8;
    if (n0 < 256) {
        const int n = n0 + nb;
        float4 blo = *(const float4*)&bin[n];
        float4 bhi = *(const float4*)&bin[n + 4];
        float bias[8] = {blo.x, blo.y, blo.z, blo.w, bhi.x, bhi.y, bhi.z, bhi.w};
#pragma unroll
        for (int i = 0; i < 8; i++) {
            int row = m0 + ty * 8 + i;
            float v[8];
#pragma unroll
            for (int p = 0; p < 4; p++) { float2 u = unpack2(acc[i][p]); v[2*p] = u.x; v[2*p+1] = u.y; }
#pragma unroll
            for (int j = 0; j < 8; j++) { float t = v[j] + bias[j]; v[j] = t * sigmoidf_(t); }
            float* dst = g_inp + (size_t)row * 256 + n;
            *(float4*)dst       = make_float4(v[0], v[1], v[2], v[3]);
            *(float4*)(dst + 4) = make_float4(v[4], v[5], v[6], v[7]);
        }
    } else if (n0 < 512) {
        const int n = n0 - 256 + nb;
        float4 blo = *(const float4*)&bg[n];
        float4 bhi = *(const float4*)&bg[n + 4];
        float bias[8] = {blo.x, blo.y, blo.z, blo.w, bhi.x, bhi.y, bhi.z, bhi.w};
#pragma unroll
        for (int i = 0; i < 8; i++) {
            int row = m0 + ty * 8 + i;
            float v[8];
#pragma unroll
            for (int p = 0; p < 4; p++) { float2 u = unpack2(acc[i][p]); v[2*p] = u.x; v[2*p+1] = u.y; }
#pragma unroll
            for (int j = 0; j < 8; j++) { float t = v[j] + bias[j]; v[j] = t * sigmoidf_(t); }
            float* dst = g_gate + (size_t)row * 256 + n;
            *(float4*)dst       = make_float4(v[0], v[1], v[2], v[3]);
            *(float4*)(dst + 4) = make_float4(v[4], v[5], v[6], v[7]);
        }
    } else {
        const int n = nb;
        float4 blo = *(const float4*)&bl[n];
        float4 bhi = *(const float4*)&bl[n + 4];
        float bias[8] = {blo.x, blo.y, blo.z, blo.w, bhi.x, bhi.y, bhi.z, bhi.w};
#pragma unroll
        for (int i = 0; i < 8; i++) {
            int row = m0 + ty * 8 + i;
            float v[8];
#pragma unroll
            for (int p = 0; p < 4; p++) { float2 u = unpack2(acc[i][p]); v[2*p] = u.x; v[2*p+1] = u.y; }
#pragma unroll
            for (int j = 0; j < 8; j++) v[j] = sigmoidf_(v[j] + bias[j]);
            float* dst = g_lam + (size_t)row * 128 + n;
            *(float4*)dst       = make_float4(v[0], v[1], v[2], v[3]);
            *(float4*)(dst + 4) = make_float4(v[4], v[5], v[6], v[7]);
        }
    }
}

// =====================================================================
// K2: scans along H (axis 0). fwd(theta_f) writes acc; rev(theta_r) RMW.
// =====================================================================
__global__ void k2_hscan(const float* __restrict__ thf, const float* __restrict__ thr_)
{
    int idx = blockIdx.x * blockDim.x + threadIdx.x;   // 0..131071
    int d  = idx & 127;
    int wb = idx >> 7;                                 // w*8+b
    int base = wb * 128 + d;

    const float2* __restrict__ inp2 = (const float2*)g_inp;

    {
        float t = thf[d];
        float cf = cosf(t), sf = sinf(t);
        float hr = 0.f, hi = 0.f;
        int off = base;
#pragma unroll 4
        for (int h = 0; h < 128; h++, off += 131072) {
            float lam = g_lam[off];
            float2 p  = inp2[off];
            float a = lam * cf, b = lam * sf, om = 1.f - lam;
            float nr = a * hr - b * hi + om * p.x;
            float ni = a * hi + b * hr + om * p.y;
            hr = nr; hi = ni;
            g_acc[off] = make_float2(hr, hi);
        }
    }
    {
        float t = thr_[d];
        float cr = cosf(t), sr = sinf(t);
        float hr = 0.f, hi = 0.f;
        int off = base + 127 * 131072;
#pragma unroll 4
        for (int h = 0; h < 128; h++, off -= 131072) {
            float lam = g_lam[off];
            float2 p  = inp2[off];
            float a = lam * cr, b = lam * sr, om = 1.f - lam;
            float nr = a * hr - b * hi + om * p.x;
            float ni = a * hi + b * hr + om * p.y;
            hr = nr; hi = ni;
            float2 acc = g_acc[off];
            acc.x += hr; acc.y += hi;
            g_acc[off] = acc;
        }
    }
}

// =====================================================================
// K3: scans along W (axis 1). Both directions RMW into acc.
// =====================================================================
__global__ void k3_wscan(const float* __restrict__ thf, const float* __restrict__ thr_)
{
    int idx = blockIdx.x * blockDim.x + threadIdx.x;
    int d = idx & 127;
    int b = (idx >> 7) & 7;
    int h = idx >> 10;
    int base = (h * 1024 + b) * 128 + d;

    const float2* __restrict__ inp2 = (const float2*)g_inp;

    {
        float t = thf[d];
        float cf = cosf(t), sf = sinf(t);
        float hr = 0.f, hi = 0.f;
        int off = base;
#pragma unroll 4
        for (int w = 0; w < 128; w++, off += 1024) {
            float lam = g_lam[off];
            float2 p  = inp2[off];
            float a = lam * cf, bb = lam * sf, om = 1.f - lam;
            float nr = a * hr - bb * hi + om * p.x;
            float ni = a * hi + bb * hr + om * p.y;
            hr = nr; hi = ni;
            float2 acc = g_acc[off];
            acc.x += hr; acc.y += hi;
            g_acc[off] = acc;
        }
    }
    {
        float t = thr_[d];
        float cr = cosf(t), sr = sinf(t);
        float hr = 0.f, hi = 0.f;
        int off = base + 127 * 1024;
#pragma unroll 4
        for (int w = 0; w < 128; w++, off -= 1024) {
            float lam = g_lam[off];
            float2 p  = inp2[off];
            float a = lam * cr, bb = lam * sr, om = 1.f - lam;
            float nr = a * hr - bb * hi + om * p.x;
            float ni = a * hi + bb * hr + om * p.y;
            hr = nr; hi = ni;
            float2 acc = g_acc[off];
            acc.x += hr; acc.y += hi;
            g_acc[off] = acc;
        }
    }
}

// =====================================================================
// K4: LN(256)*ln_w+ln_b, *gate -> feat smem [64][260]; GEMM @ W_out + b_out.
//     256 threads, 4x8 microtile, FFMA2.
// =====================================================================
#define FLD 260   // feat row stride (floats)

__global__ void __launch_bounds__(256, 1)
k4_out_gemm(const float* __restrict__ Wout, const float* __restrict__ bout,
            const float* __restrict__ lnw,  const float* __restrict__ lnb,
            float* __restrict__ out)
{
    extern __shared__ float sm[];
    float* feat = sm;               // [64][FLD]
    float* Ws   = sm + 64 * FLD;    // [256][128]

    const int tid = threadIdx.x;
    const int m0 = blockIdx.x * 64;

    // ---- load W_out (256x128) with float4
    {
        float4* Ws4 = (float4*)Ws;
        const float4* W4 = (const float4*)Wout;
#pragma unroll
        for (int t = 0; t < 32; t++) Ws4[tid + t * 256] = W4[tid + t * 256];
    }

    // ---- producer: LN stats + normalized, gated feature into smem
    {
        int r = tid >> 2;          // local row 0..63
        int q = tid & 3;           // 4 lanes cooperate per row
        int row = m0 + r;
        const float2* accp = g_acc + (size_t)row * 128;

        float sum = 0.f, ss = 0.f;
#pragma unroll
        for (int t = 0; t < 32; t++) {
            int dd = q + t * 4;
            float2 v = accp[dd];
            sum += v.x + v.y;
            ss  += v.x * v.x + v.y * v.y;
        }
        sum += __shfl_xor_sync(0xffffffffu, sum, 1);
        sum += __shfl_xor_sync(0xffffffffu, sum, 2);
        ss  += __shfl_xor_sync(0xffffffffu, ss, 1);
        ss  += __shfl_xor_sync(0xffffffffu, ss, 2);

        float mu   = sum * (1.0f / 256.0f);
        float var  = ss * (1.0f / 256.0f) - mu * mu;
        float rstd = rsqrtf(var + 1e-5f);

        const float* gr = g_gate + (size_t)row * 256;
#pragma unroll
        for (int t = 0; t < 32; t++) {
            int dd = q + t * 4;
            float2 v = accp[dd];
            float fr = ((v.x - mu) * rstd * lnw[dd]       + lnb[dd])       * gr[dd];
            float fi = ((v.y - mu) * rstd * lnw[128 + dd] + lnb[128 + dd]) * gr[128 + dd];
            feat[r * FLD + dd]       = fr;
            feat[r * FLD + 128 + dd] = fi;
        }
    }
    __syncthreads();

    // ---- GEMM: feat(64x256) @ Ws(256x128), 4x8 microtile, FFMA2
    const int ty = tid >> 4;     // rows ty*4
    const int tx = tid & 15;     // cols tx*8
    const unsigned ws_base = (unsigned)__cvta_generic_to_shared(Ws) + tx * 32;

    ull acc[4][4];
#pragma unroll
    for (int i = 0; i < 4; i++)
#pragma unroll
        for (int p = 0; p < 4; p++) acc[i][p] = 0ULL;

#pragma unroll 2
    for (int kc = 0; kc < 64; kc++) {
        ull b[4][4];
#pragma unroll
        for (int kk = 0; kk < 4; kk++) {
            unsigned ad = ws_base + (unsigned)((kc * 4 + kk) * 512);
            lds2(b[kk][0], b[kk][1], ad);
            lds2(b[kk][2], b[kk][3], ad + 16);
        }
#pragma unroll
        for (int i = 0; i < 4; i++) {
            float4 a = *(const float4*)&feat[(ty * 4 + i) * FLD + kc * 4];
            ull a0 = pack2(a.x), a1 = pack2(a.y), a2 = pack2(a.z), a3 = pack2(a.w);
#pragma unroll
            for (int p = 0; p < 4; p++) {
                ffma2(acc[i][p], a0, b[0][p]);
                ffma2(acc[i][p], a1, b[1][p]);
                ffma2(acc[i][p], a2, b[2][p]);
                ffma2(acc[i][p], a3, b[3][p]);
            }
        }
    }

    // ---- epilogue
    float4 blo = *(const float4*)&bout[tx * 8];
    float4 bhi = *(const float4*)&bout[tx * 8 + 4];
    float bias[8] = {blo.x, blo.y, blo.z, blo.w, bhi.x, bhi.y, bhi.z, bhi.w};
#pragma unroll
    for (int i = 0; i < 4; i++) {
        int row = m0 + ty * 4 + i;
        float v[8];
#pragma unroll
        for (int p = 0; p < 4; p++) { float2 u = unpack2(acc[i][p]); v[2*p] = u.x; v[2*p+1] = u.y; }
#pragma unroll
        for (int j = 0; j < 8; j++) v[j] += bias[j];
        float* dst = out + (size_t)row * 128 + tx * 8;
        *(float4*)dst       = make_float4(v[0], v[1], v[2], v[3]);
        *(float4*)(dst + 4) = make_float4(v[4], v[5], v[6], v[7]);
    }
}

// =====================================================================
extern "C" void kernel_launch(void* const* d_in, const int* in_sizes, int n_in,
                              void* d_out, int out_size)
{
    const float* x    = (const float*)d_in[0];
    const float* Win  = (const float*)d_in[1];
    const float* bin  = (const float*)d_in[2];
    const float* Wl   = (const float*)d_in[3];
    const float* bl   = (const float*)d_in[4];
    const float* thf  = (const float*)d_in[5];
    const float* thr_ = (const float*)d_in[6];
    const float* Wg   = (const float*)d_in[7];
    const float* bg   = (const float*)d_in[8];
    const float* Wout = (const float*)d_in[9];
    const float* bout = (const float*)d_in[10];
    const float* lnw  = (const float*)d_in[11];
    const float* lnb  = (const float*)d_in[12];
    float* out = (float*)d_out;

    const int SM1 = 128 * 128 * 2 * 4;                 // 131072
    const int SM4 = (64 * FLD + 256 * 128) * 4;        // 197632
    cudaFuncSetAttribute(k1_in_gemm,  cudaFuncAttributeMaxDynamicSharedMemorySize, SM1);
    cudaFuncSetAttribute(k4_out_gemm, cudaFuncAttributeMaxDynamicSharedMemorySize, SM4);

    dim3 g1(640 / 128, MM / 128);                      // (5, 1024)
    k1_in_gemm<<<g1, 256, SM1>>>(x, Win, bin, Wl, bl, Wg, bg);

    k2_hscan<<<MM / 256, 256>>>(thf, thr_);
    k3_wscan<<<MM / 256, 256>>>(thf, thr_);

    k4_out_gemm<<<MM / 64, 256, SM4>>>(Wout, bout, lnw, lnb, out);
}